// round 2
// baseline (speedup 1.0000x reference)
#include <cuda_runtime.h>
#include <cstdint>

// Problem constants (fixed by the reference).
#define B_DIM 16
#define N_DIM 1024
#define T_DIM 100
#define NE 16777216u          // B*N*N
#define HALF 8388608u         // NE/2
#define NN_LOG2 20            // N*N = 2^20

#define THREADS 256
#define GRID 2048

__device__ double g_partial[GRID];

// ---------------- Threefry-2x32, key = (0, 42) ----------------
__device__ __forceinline__ void tf_round(uint32_t& x0, uint32_t& x1, int r) {
    x0 += x1;
    x1 = __funnelshift_l(x1, x1, r);
    x1 ^= x0;
}

__device__ __forceinline__ uint2 threefry(uint32_t x0, uint32_t x1) {
    const uint32_t ks0 = 0u;
    const uint32_t ks1 = 42u;
    const uint32_t ks2 = 42u ^ 0x1BD11BDAu;
    x0 += ks0; x1 += ks1;
    tf_round(x0, x1, 13); tf_round(x0, x1, 15); tf_round(x0, x1, 26); tf_round(x0, x1, 6);
    x0 += ks1; x1 += ks2 + 1u;
    tf_round(x0, x1, 17); tf_round(x0, x1, 29); tf_round(x0, x1, 16); tf_round(x0, x1, 24);
    x0 += ks2; x1 += ks0 + 2u;
    tf_round(x0, x1, 13); tf_round(x0, x1, 15); tf_round(x0, x1, 26); tf_round(x0, x1, 6);
    x0 += ks0; x1 += ks1 + 3u;
    tf_round(x0, x1, 17); tf_round(x0, x1, 29); tf_round(x0, x1, 16); tf_round(x0, x1, 24);
    x0 += ks1; x1 += ks2 + 4u;
    tf_round(x0, x1, 13); tf_round(x0, x1, 15); tf_round(x0, x1, 26); tf_round(x0, x1, 6);
    x0 += ks2; x1 += ks0 + 5u;
    return make_uint2(x0, x1);
}

// bits -> uniform in [tiny, 1), bit-matching JAX's _uniform.
__device__ __forceinline__ float bits_to_u01(uint32_t bits) {
    float f = __uint_as_float(0x3f800000u | (bits >> 9)) - 1.0f;
    return fmaxf(f, 1.17549435e-38f);
}

// One element's BCE contribution.
__device__ __forceinline__ float elem_contrib(
    unsigned idx, uint32_t bits0, uint32_t bits1,
    const int* __restrict__ adj, const float* __restrict__ qa,
    const float* sQt, const int* sT, float L00, float L10)
{
    const int b  = (int)(idx >> NN_LOG2);
    const int a0 = adj[idx];
    const float qav = qa[idx];

    const int tb  = sT[b];
    const int tm1 = (tb == 0) ? (T_DIM - 1) : (tb - 1);

    // forward probs q_fwd = Qt[tb][a0][:]
    const float q0 = sQt[tb * 4 + a0 * 2 + 0];
    const float q1 = sQt[tb * 4 + a0 * 2 + 1];

    // gumbel-max via monotone transform: argmax(log q + g) ==
    //   adj_t = 1  iff  q1 * (-log2 u0) > q0 * (-log2 u1)
    const float Lg0 = -__log2f(bits_to_u01(bits0));
    const float Lg1 = -__log2f(bits_to_u01(bits1));
    const int at = (q1 * Lg0 > q0 * Lg1) ? 1 : 0;

    const float like0  = at ? L10 : L00;                 // Qt[0][adj_t][0]
    const float prior0 = sQt[tm1 * 4 + a0 * 2 + 0];      // Qt[t-1][a0][0]
    const float ev     = at ? q1 : q0;                   // Qt[t][a0][adj_t]

    const float qt = __fdividef(like0 * prior0, ev);     // q_target

    const float logp   = fmaxf(__logf(qav), -100.0f);
    const float log1mp = fmaxf(__logf(1.0f - qav), -100.0f);

    // qt*logp + (1-qt)*log1mp
    return fmaf(qt, logp - log1mp, log1mp);
}

__global__ void __launch_bounds__(THREADS)
diffusion_main(const int* __restrict__ adj, const int* __restrict__ t,
               const float* __restrict__ qa, const float* __restrict__ Qt)
{
    __shared__ float sQt[T_DIM * 4];
    __shared__ int   sT[B_DIM];
    for (int i = threadIdx.x; i < T_DIM * 4; i += THREADS) sQt[i] = Qt[i];
    if (threadIdx.x < B_DIM) sT[threadIdx.x] = t[threadIdx.x];
    __syncthreads();

    const float L00 = sQt[0]; // Qt[0][0][0]
    const float L10 = sQt[2]; // Qt[0][1][0]

    float acc = 0.0f;
    const unsigned stride = (unsigned)GRID * THREADS;
    for (unsigned base = blockIdx.x * THREADS + threadIdx.x; base < HALF; base += stride) {
        // counters: element `base` uses y0 of both calls; `base+HALF` uses y1.
        const uint2 r0 = threefry(2u * base,      2u * base + NE);
        const uint2 r1 = threefry(2u * base + 1u, 2u * base + 1u + NE);
        acc += elem_contrib(base,        r0.x, r1.x, adj, qa, sQt, sT, L00, L10);
        acc += elem_contrib(base + HALF, r0.y, r1.y, adj, qa, sQt, sT, L00, L10);
    }

    // deterministic block reduction: warp shuffles, then warp leaders via smem.
    #pragma unroll
    for (int off = 16; off > 0; off >>= 1)
        acc += __shfl_down_sync(0xffffffffu, acc, off);

    __shared__ float warp_sums[THREADS / 32];
    if ((threadIdx.x & 31) == 0) warp_sums[threadIdx.x >> 5] = acc;
    __syncthreads();
    if (threadIdx.x == 0) {
        double s = 0.0;
        #pragma unroll
        for (int w = 0; w < THREADS / 32; w++) s += (double)warp_sums[w];
        g_partial[blockIdx.x] = s;
    }
}

__global__ void __launch_bounds__(256)
diffusion_reduce(float* __restrict__ out)
{
    __shared__ double sh[256];
    double s = 0.0;
    for (int i = threadIdx.x; i < GRID; i += 256) s += g_partial[i];
    sh[threadIdx.x] = s;
    __syncthreads();
    #pragma unroll
    for (int off = 128; off > 0; off >>= 1) {
        if (threadIdx.x < off) sh[threadIdx.x] += sh[threadIdx.x + off];
        __syncthreads();
    }
    if (threadIdx.x == 0)
        out[0] = (float)(-sh[0] / (double)NE);
}

extern "C" void kernel_launch(void* const* d_in, const int* in_sizes, int n_in,
                              void* d_out, int out_size)
{
    const int*   adj = (const int*)d_in[0];    // adj_start [B,N,N] int32
    const int*   t   = (const int*)d_in[1];    // t [B] int32
    const float* qa  = (const float*)d_in[2];  // q_approx [B*N*N] float32
    const float* Qt  = (const float*)d_in[3];  // Qt [T,2,2] float32
    float* out = (float*)d_out;

    diffusion_main<<<GRID, THREADS>>>(adj, t, qa, Qt);
    diffusion_reduce<<<1, 256>>>(out);
}

// round 5
// speedup vs baseline: 1.1736x; 1.1736x over previous
#include <cuda_runtime.h>
#include <cstdint>

// Problem constants (fixed by the reference).
#define T_DIM 100
#define NE    16777216u      // B*N*N
#define HALF  8388608u       // NE/2
#define QUART 4194304u       // HALF/2  (j-space: one j covers elements 2j,2j+1,2j+HALF,2j+1+HALF)

#define THREADS 128
#define GRID    1184         // 148 SMs * 8 CTAs -> exact per-SM balance

__device__ double   g_partial[GRID];
__device__ unsigned g_count = 0;     // self-resetting across graph replays

// ---------------- Threefry-2x32, key = (0, 42) ----------------
__device__ __forceinline__ void tf_round(uint32_t& x0, uint32_t& x1, int r) {
    x0 += x1;
    x1 = __funnelshift_l(x1, x1, r);
    x1 ^= x0;
}

__device__ __forceinline__ uint2 threefry(uint32_t x0, uint32_t x1) {
    const uint32_t ks0 = 0u;
    const uint32_t ks1 = 42u;
    const uint32_t ks2 = 42u ^ 0x1BD11BDAu;
    x0 += ks0; x1 += ks1;
    tf_round(x0, x1, 13); tf_round(x0, x1, 15); tf_round(x0, x1, 26); tf_round(x0, x1, 6);
    x0 += ks1; x1 += ks2 + 1u;
    tf_round(x0, x1, 17); tf_round(x0, x1, 29); tf_round(x0, x1, 16); tf_round(x0, x1, 24);
    x0 += ks2; x1 += ks0 + 2u;
    tf_round(x0, x1, 13); tf_round(x0, x1, 15); tf_round(x0, x1, 26); tf_round(x0, x1, 6);
    x0 += ks0; x1 += ks1 + 3u;
    tf_round(x0, x1, 17); tf_round(x0, x1, 29); tf_round(x0, x1, 16); tf_round(x0, x1, 24);
    x0 += ks1; x1 += ks2 + 4u;
    tf_round(x0, x1, 13); tf_round(x0, x1, 15); tf_round(x0, x1, 26); tf_round(x0, x1, 6);
    x0 += ks2; x1 += ks0 + 5u;
    return make_uint2(x0, x1);
}

// JAX uniform: bitcast(0x3f800000 | bits>>9) - 1.0  (tiny-clamp dropped:
// fires w.p. 2^-23 and the induced log2 = -inf resolves the comparison the
// same way as the clamped value except on measure-~1e-10 joint events).
__device__ __forceinline__ float u01(uint32_t bits) {
    return __uint_as_float(0x3f800000u | (bits >> 9)) - 1.0f;
}

// Contribution of one element, in log2 units (scale by ln2 once at the end).
// e = {r = q0/q1, qt(at=0), qt(at=1), unused}
__device__ __forceinline__ float elem(uint32_t bits0, uint32_t bits1,
                                      float4 e, float qav)
{
    const float lg0 = __log2f(u01(bits0));
    const float lg1 = __log2f(u01(bits1));
    // adj_t = 1  iff  q1*(-log u0) > q0*(-log u1)  <=>  lg0 < r*lg1  (lg's <= 0)
    const float qt  = (lg0 < e.x * lg1) ? e.z : e.y;
    const float l2p = __log2f(qav);          // clamps never fire: qa in [1e-4, 1-1e-4]
    const float l2m = __log2f(1.0f - qav);
    return fmaf(qt, l2p - l2m, l2m);         // qt*l2p + (1-qt)*l2m
}

__global__ void __launch_bounds__(THREADS, 8)
diffusion_main(const int* __restrict__ adj, const int* __restrict__ t,
               const float* __restrict__ qa, const float* __restrict__ Qt,
               float* __restrict__ out)
{
    // Per-(b, a0) precomputed table: r = q0/q1, c0 = qt(adj_t=0), c1 = qt(adj_t=1).
    __shared__ float4 sTab[32];
    if (threadIdx.x < 32) {
        const int b  = threadIdx.x >> 1;
        const int a0 = threadIdx.x & 1;
        const int tb  = t[b];
        const int tm1 = tb ? (tb - 1) : (T_DIM - 1);   // JAX wraps t-1 = -1 -> T-1
        const float q0 = Qt[tb * 4 + a0 * 2 + 0];
        const float q1 = Qt[tb * 4 + a0 * 2 + 1];
        const float p0 = Qt[tm1 * 4 + a0 * 2 + 0];     // prior: Qt[t-1][a0][0]
        const float L00 = Qt[0];                       // Qt[0][0][0]
        const float L10 = Qt[2];                       // Qt[0][1][0]
        sTab[threadIdx.x] = make_float4(q0 / q1, L00 * p0 / q0, L10 * p0 / q1, 0.0f);
    }
    __syncthreads();

    const int2*   adj2 = (const int2*)adj;
    const float2* qa2  = (const float2*)qa;

    float acc = 0.0f;
    const unsigned stride = (unsigned)GRID * THREADS;
    for (unsigned j = (unsigned)blockIdx.x * THREADS + threadIdx.x; j < QUART; j += stride) {
        // Issue long-latency loads first; ~280 threefry instrs hide them.
        const int2   a_lo = adj2[j];
        const int2   a_hi = adj2[j + QUART];
        const float2 q_lo = qa2[j];
        const float2 q_hi = qa2[j + QUART];

        // Exact JAX counter mapping (validated in the passing kernel):
        // element e < HALF uses y0 of calls (2e, 2e+NE), (2e+1, 2e+1+NE);
        // element e + HALF uses y1 of the same two calls.
        const uint2 c0 = threefry(4u * j,      4u * j      + NE);
        const uint2 c1 = threefry(4u * j + 1u, 4u * j + 1u + NE);
        const uint2 c2 = threefry(4u * j + 2u, 4u * j + 2u + NE);
        const uint2 c3 = threefry(4u * j + 3u, 4u * j + 3u + NE);

        const unsigned b2lo = (j >> 19) * 2u;   // b = (2j)>>20; key = b*2 + a0
        // b for (e + HALF) is b_lo + 8  ->  key offset +16
        acc += elem(c0.x, c1.x, sTab[b2lo +        (unsigned)a_lo.x], q_lo.x);
        acc += elem(c2.x, c3.x, sTab[b2lo +        (unsigned)a_lo.y], q_lo.y);
        acc += elem(c0.y, c1.y, sTab[b2lo + 16u +  (unsigned)a_hi.x], q_hi.x);
        acc += elem(c2.y, c3.y, sTab[b2lo + 16u +  (unsigned)a_hi.y], q_hi.y);
    }

    // ---- deterministic in-kernel reduction ----
    #pragma unroll
    for (int off = 16; off > 0; off >>= 1)
        acc += __shfl_down_sync(0xffffffffu, acc, off);

    __shared__ float wsum[THREADS / 32];
    if ((threadIdx.x & 31) == 0) wsum[threadIdx.x >> 5] = acc;
    __syncthreads();

    __shared__ bool isLast;
    if (threadIdx.x == 0) {
        double s = 0.0;
        #pragma unroll
        for (int w = 0; w < THREADS / 32; w++) s += (double)wsum[w];
        g_partial[blockIdx.x] = s;
        __threadfence();
        isLast = (atomicAdd(&g_count, 1u) == GRID - 1u);
    }
    __syncthreads();

    if (isLast) {
        __threadfence();  // acquire: g_partial writes from all blocks visible
        double s = 0.0;
        for (int i = threadIdx.x; i < GRID; i += THREADS) s += g_partial[i];
        __shared__ double sh[THREADS];
        sh[threadIdx.x] = s;
        __syncthreads();
        #pragma unroll
        for (int off = THREADS / 2; off > 0; off >>= 1) {
            if (threadIdx.x < off) sh[threadIdx.x] += sh[threadIdx.x + off];
            __syncthreads();
        }
        if (threadIdx.x == 0) {
            // accumulated in log2 units -> scale by ln2; loss = -mean
            out[0] = (float)(-(sh[0] * 0.69314718055994530942) / (double)NE);
            g_count = 0;   // reset for next graph replay
        }
    }
}

extern "C" void kernel_launch(void* const* d_in, const int* in_sizes, int n_in,
                              void* d_out, int out_size)
{
    const int*   adj = (const int*)d_in[0];    // adj_start [B,N,N] int32
    const int*   t   = (const int*)d_in[1];    // t [B] int32
    const float* qa  = (const float*)d_in[2];  // q_approx [B*N*N] float32
    const float* Qt  = (const float*)d_in[3];  // Qt [T,2,2] float32
    float* out = (float*)d_out;

    diffusion_main<<<GRID, THREADS>>>(adj, t, qa, Qt, out);
}

// round 6
// speedup vs baseline: 1.1949x; 1.0181x over previous
#include <cuda_runtime.h>
#include <cstdint>

// Problem constants (fixed by the reference).
#define T_DIM 100
#define NE    16777216u      // B*N*N
#define HALF  8388608u       // NE/2
#define QUART 4194304u       // HALF/2

#define THREADS 128
#define NCTA_PER_SM 12
#define GRID (148 * NCTA_PER_SM)   // 1776: one exact full wave, 48 warps/SM

__device__ double   g_partial[GRID];
__device__ unsigned g_count = 0;     // self-resetting across graph replays

#define KS2 (42u ^ 0x1BD11BDAu)

// add pinned to the fma pipe: d = b*one + a  (one == 1, runtime-opaque)
__device__ __forceinline__ uint32_t addm(uint32_t a, uint32_t b, uint32_t one) {
    uint32_t d;
    asm("mad.lo.u32 %0, %1, %2, %3;" : "=r"(d) : "r"(b), "r"(one), "r"(a));
    return d;
}
// add-immediate pinned to the fma pipe: d = one*C + a
template <uint32_t C>
__device__ __forceinline__ uint32_t addc(uint32_t a, uint32_t one) {
    uint32_t d;
    asm("mad.lo.u32 %0, %1, %2, %3;" : "=r"(d) : "r"(one), "n"(C), "r"(a));
    return d;
}

__device__ __forceinline__ void tf_round(uint32_t& x0, uint32_t& x1, int r, uint32_t one) {
    x0 = addm(x0, x1, one);                 // IMAD (fma pipe)
    x1 = __funnelshift_l(x1, x1, r);        // SHF  (alu pipe)
    x1 ^= x0;                               // LOP3 (alu pipe)
}

// ---------------- Threefry-2x32, key = (0, 42) ----------------
__device__ __forceinline__ uint2 threefry(uint32_t x0, uint32_t x1, uint32_t one) {
    x1 = addc<42u>(x1, one);                          // x0 += ks0 (=0): dropped
    tf_round(x0, x1, 13, one); tf_round(x0, x1, 15, one);
    tf_round(x0, x1, 26, one); tf_round(x0, x1,  6, one);
    x0 = addc<42u>(x0, one);  x1 = addc<KS2 + 1u>(x1, one);
    tf_round(x0, x1, 17, one); tf_round(x0, x1, 29, one);
    tf_round(x0, x1, 16, one); tf_round(x0, x1, 24, one);
    x0 = addc<KS2>(x0, one);  x1 = addc<2u>(x1, one);
    tf_round(x0, x1, 13, one); tf_round(x0, x1, 15, one);
    tf_round(x0, x1, 26, one); tf_round(x0, x1,  6, one);
    /* x0 += ks0 (=0): dropped */            x1 = addc<45u>(x1, one);
    tf_round(x0, x1, 17, one); tf_round(x0, x1, 29, one);
    tf_round(x0, x1, 16, one); tf_round(x0, x1, 24, one);
    x0 = addc<42u>(x0, one);  x1 = addc<KS2 + 4u>(x1, one);
    tf_round(x0, x1, 13, one); tf_round(x0, x1, 15, one);
    tf_round(x0, x1, 26, one); tf_round(x0, x1,  6, one);
    x0 = addc<KS2>(x0, one);  x1 = addc<5u>(x1, one);
    return make_uint2(x0, x1);
}

// JAX uniform: bitcast(0x3f800000 | bits>>9) - 1.0  (tiny-clamp dropped:
// fires w.p. 2^-23; the resulting -inf log resolves the comparison identically
// except on measure-~1e-10 joint events).
__device__ __forceinline__ float u01(uint32_t bits) {
    return __uint_as_float(0x3f800000u | (bits >> 9)) - 1.0f;
}

// Contribution of one element, in log2 units (scaled by ln2 once at the end).
// e = {r = q0/q1, qt(adj_t=0), qt(adj_t=1), unused}
__device__ __forceinline__ float elem(uint32_t bits0, uint32_t bits1,
                                      float4 e, float qav)
{
    const float lg0 = __log2f(u01(bits0));
    const float lg1 = __log2f(u01(bits1));
    // adj_t = 1  iff  q1*(-log u0) > q0*(-log u1)  <=>  lg0 < r*lg1  (lg's <= 0)
    const float qt  = (lg0 < e.x * lg1) ? e.z : e.y;
    const float l2p = __log2f(qav);          // -100 clamps never fire: qa in [1e-4, 1-1e-4]
    const float l2m = __log2f(1.0f - qav);
    return fmaf(qt, l2p - l2m, l2m);         // qt*l2p + (1-qt)*l2m
}

__global__ void __launch_bounds__(THREADS, NCTA_PER_SM)
diffusion_main(const int* __restrict__ adj, const int* __restrict__ t,
               const float* __restrict__ qa, const float* __restrict__ Qt,
               float* __restrict__ out)
{
    // Per-(b, a0) precomputed table: r = q0/q1, c0 = qt(adj_t=0), c1 = qt(adj_t=1).
    __shared__ float4 sTab[32];
    if (threadIdx.x < 32) {
        const int b  = threadIdx.x >> 1;
        const int a0 = threadIdx.x & 1;
        const int tb  = t[b];
        const int tm1 = tb ? (tb - 1) : (T_DIM - 1);   // JAX wraps t-1 = -1 -> T-1
        const float q0 = Qt[tb * 4 + a0 * 2 + 0];
        const float q1 = Qt[tb * 4 + a0 * 2 + 1];
        const float p0 = Qt[tm1 * 4 + a0 * 2 + 0];     // prior: Qt[t-1][a0][0]
        const float L00 = Qt[0];                       // Qt[0][0][0]
        const float L10 = Qt[2];                       // Qt[0][1][0]
        sTab[threadIdx.x] = make_float4(q0 / q1, L00 * p0 / q0, L10 * p0 / q1, 0.0f);
    }
    __syncthreads();

    // Runtime-opaque 1 so ptxas cannot strength-reduce the IMADs back to IADD.
    const uint32_t one = (Qt[0] != 0.0f) ? 1u : 0u;

    const int2*   adj2 = (const int2*)adj;
    const float2* qa2  = (const float2*)qa;

    float a0v = 0.0f, a1v = 0.0f, a2v = 0.0f, a3v = 0.0f;
    const unsigned stride = (unsigned)GRID * THREADS;
    for (unsigned j = (unsigned)blockIdx.x * THREADS + threadIdx.x; j < QUART; j += stride) {
        // Long-latency loads first; ~300 threefry instrs hide them.
        const int2   a_lo = adj2[j];
        const int2   a_hi = adj2[j + QUART];
        const float2 q_lo = qa2[j];
        const float2 q_hi = qa2[j + QUART];

        // Exact JAX counter mapping (validated):
        // element e < HALF uses y0 of calls (2e, 2e+NE), (2e+1, 2e+1+NE);
        // element e + HALF uses y1 of the same two calls.
        const uint2 c0 = threefry(4u * j,      4u * j      + NE, one);
        const uint2 c1 = threefry(4u * j + 1u, 4u * j + 1u + NE, one);
        const uint2 c2 = threefry(4u * j + 2u, 4u * j + 2u + NE, one);
        const uint2 c3 = threefry(4u * j + 3u, 4u * j + 3u + NE, one);

        const unsigned b2lo = (j >> 19) * 2u;   // b = (2j)>>20; key = b*2 + a0
        // b for (e + HALF) is b_lo + 8  ->  table offset +16
        a0v += elem(c0.x, c1.x, sTab[b2lo +       (unsigned)a_lo.x], q_lo.x);
        a1v += elem(c2.x, c3.x, sTab[b2lo +       (unsigned)a_lo.y], q_lo.y);
        a2v += elem(c0.y, c1.y, sTab[b2lo + 16u + (unsigned)a_hi.x], q_hi.x);
        a3v += elem(c2.y, c3.y, sTab[b2lo + 16u + (unsigned)a_hi.y], q_hi.y);
    }
    float acc = (a0v + a1v) + (a2v + a3v);

    // ---- deterministic in-kernel reduction ----
    #pragma unroll
    for (int off = 16; off > 0; off >>= 1)
        acc += __shfl_down_sync(0xffffffffu, acc, off);

    __shared__ float wsum[THREADS / 32];
    if ((threadIdx.x & 31) == 0) wsum[threadIdx.x >> 5] = acc;
    __syncthreads();

    __shared__ bool isLast;
    if (threadIdx.x == 0) {
        double s = 0.0;
        #pragma unroll
        for (int w = 0; w < THREADS / 32; w++) s += (double)wsum[w];
        g_partial[blockIdx.x] = s;
        __threadfence();
        isLast = (atomicAdd(&g_count, 1u) == GRID - 1u);
    }
    __syncthreads();

    if (isLast) {
        __threadfence();  // acquire: all g_partial writes visible
        double s = 0.0;
        for (int i = threadIdx.x; i < GRID; i += THREADS) s += g_partial[i];
        __shared__ double sh[THREADS];
        sh[threadIdx.x] = s;
        __syncthreads();
        #pragma unroll
        for (int off = THREADS / 2; off > 0; off >>= 1) {
            if (threadIdx.x < off) sh[threadIdx.x] += sh[threadIdx.x + off];
            __syncthreads();
        }
        if (threadIdx.x == 0) {
            // accumulated in log2 units -> scale by ln2; loss = -mean
            out[0] = (float)(-(sh[0] * 0.69314718055994530942) / (double)NE);
            g_count = 0;   // reset for next graph replay
        }
    }
}

extern "C" void kernel_launch(void* const* d_in, const int* in_sizes, int n_in,
                              void* d_out, int out_size)
{
    const int*   adj = (const int*)d_in[0];    // adj_start [B,N,N] int32
    const int*   t   = (const int*)d_in[1];    // t [B] int32
    const float* qa  = (const float*)d_in[2];  // q_approx [B*N*N] float32
    const float* Qt  = (const float*)d_in[3];  // Qt [T,2,2] float32
    float* out = (float*)d_out;

    diffusion_main<<<GRID, THREADS>>>(adj, t, qa, Qt, out);
}